// round 4
// baseline (speedup 1.0000x reference)
#include <cuda_runtime.h>
#include <cuda_bf16.h>
#include <math.h>
#include <stdint.h>

#define NTOK   2048
#define DMODEL 512
#define NHEADS 8
#define DHEAD  64
#define CONDD  768
#define HH     32
#define WW     32

// ---------------- scratch ----------------
__device__ float g_ns [2 * DMODEL];
__device__ float g_xn [NTOK * DMODEL];
__device__ float g_qkv[NTOK * 3 * DMODEL];
__device__ float g_o  [NTOK * DMODEL];

__device__ __forceinline__ float warp_sum(float v) {
    v += __shfl_xor_sync(0xffffffffu, v, 16);
    v += __shfl_xor_sync(0xffffffffu, v, 8);
    v += __shfl_xor_sync(0xffffffffu, v, 4);
    v += __shfl_xor_sync(0xffffffffu, v, 2);
    v += __shfl_xor_sync(0xffffffffu, v, 1);
    return v;
}
__device__ __forceinline__ uint32_t smem_u32(const void* p) {
    return (uint32_t)__cvta_generic_to_shared((void*)p);
}
#define SWZ(o) ((o) ^ ((((uint32_t)(o)) >> 3) & 0x70))

__device__ __forceinline__ void ldm_x4(uint32_t addr, uint32_t& r0, uint32_t& r1,
                                       uint32_t& r2, uint32_t& r3) {
    asm volatile("ldmatrix.sync.aligned.m8n8.x4.shared.b16 {%0,%1,%2,%3}, [%4];"
                 : "=r"(r0), "=r"(r1), "=r"(r2), "=r"(r3) : "r"(addr));
}
__device__ __forceinline__ void mma_bf16(float& c0, float& c1, float& c2, float& c3,
                                         uint32_t a0, uint32_t a1, uint32_t a2, uint32_t a3,
                                         uint32_t b0, uint32_t b1) {
    asm volatile(
        "mma.sync.aligned.m16n8k16.row.col.f32.bf16.bf16.f32 "
        "{%0,%1,%2,%3}, {%4,%5,%6,%7}, {%8,%9}, {%0,%1,%2,%3};"
        : "+f"(c0), "+f"(c1), "+f"(c2), "+f"(c3)
        : "r"(a0), "r"(a1), "r"(a2), "r"(a3), "r"(b0), "r"(b1));
}

// fp32x8 -> bf16 hi/lo uint4 pair
__device__ __forceinline__ void cvt_hilo4(float4 f0, float4 f1, uint4& hi, uint4& lo) {
    __nv_bfloat162 h0 = __floats2bfloat162_rn(f0.x, f0.y);
    __nv_bfloat162 h1 = __floats2bfloat162_rn(f0.z, f0.w);
    __nv_bfloat162 h2 = __floats2bfloat162_rn(f1.x, f1.y);
    __nv_bfloat162 h3 = __floats2bfloat162_rn(f1.z, f1.w);
    float2 g0 = __bfloat1622float2(h0), g1 = __bfloat1622float2(h1);
    float2 g2 = __bfloat1622float2(h2), g3 = __bfloat1622float2(h3);
    __nv_bfloat162 l0 = __floats2bfloat162_rn(f0.x - g0.x, f0.y - g0.y);
    __nv_bfloat162 l1 = __floats2bfloat162_rn(f0.z - g1.x, f0.w - g1.y);
    __nv_bfloat162 l2 = __floats2bfloat162_rn(f1.x - g2.x, f1.y - g2.y);
    __nv_bfloat162 l3 = __floats2bfloat162_rn(f1.z - g3.x, f1.w - g3.y);
    hi.x = *(uint32_t*)&h0; hi.y = *(uint32_t*)&h1; hi.z = *(uint32_t*)&h2; hi.w = *(uint32_t*)&h3;
    lo.x = *(uint32_t*)&l0; lo.y = *(uint32_t*)&l1; lo.z = *(uint32_t*)&l2; lo.w = *(uint32_t*)&l3;
}

// ---------------- 1. norm_scale = cond @ w_cond^T + 1 ----------------
__global__ void cond_scale_k(const float* __restrict__ cond,
                             const float* __restrict__ w_cond,
                             float* __restrict__ ns) {
    int gw   = (blockIdx.x * blockDim.x + threadIdx.x) >> 5;
    int lane = threadIdx.x & 31;
    int n = gw >> 9, d = gw & 511;
    const float* wr = w_cond + (size_t)d * CONDD;
    const float* cr = cond   + (size_t)n * CONDD;
    float s = 0.f;
    for (int k = lane; k < CONDD; k += 32) s = fmaf(wr[k], cr[k], s);
    s = warp_sum(s);
    if (lane == 0) ns[n * DMODEL + d] = s + 1.0f;
}

// ---------------- 2. RMS norm * norm_scale (fp32 out) ----------------
__global__ void rmsnorm_k(const float* __restrict__ x,
                          const float* __restrict__ ns,
                          float* __restrict__ xn) {
    int t = blockIdx.x;
    int n = t >> 10;
    float4 v = ((const float4*)(x + (size_t)t * DMODEL))[threadIdx.x];
    float ss = v.x*v.x + v.y*v.y + v.z*v.z + v.w*v.w;
    ss = warp_sum(ss);
    __shared__ float sred[4];
    int w = threadIdx.x >> 5, l = threadIdx.x & 31;
    if (l == 0) sred[w] = ss;
    __syncthreads();
    float tot = sred[0] + sred[1] + sred[2] + sred[3];
    float inv = rsqrtf(tot * (1.0f / DMODEL) + 1e-6f);
    float4 s4 = ((const float4*)(ns + (size_t)n * DMODEL))[threadIdx.x];
    float4 o;
    o.x = v.x * s4.x * inv; o.y = v.y * s4.y * inv;
    o.z = v.z * s4.z * inv; o.w = v.w * s4.w * inv;
    ((float4*)(xn + (size_t)t * DMODEL))[threadIdx.x] = o;
}

// ---------------- mma.sync GEMM, fused fp32->hi/lo, optional fused qk-norm+rope ----------------
// C[M][BN*gx] = A[M][K] @ B^T, tiles 128 x (BNG*32).  256 threads, 8 warps.
template<int BNG, bool ADD, bool QKNORM>
__global__ void __launch_bounds__(256, 1)
gemm_mma(const float* __restrict__ A, const float* __restrict__ B,
         const float* __restrict__ skip, float* __restrict__ C,
         const float* __restrict__ pos, const float* __restrict__ scl,
         int M, int N, int Kd) {
    constexpr int BN = BNG * 32;
    extern __shared__ char smraw[];
    const uint32_t sb = smem_u32(smraw);
    const uint32_t SA_H = 0, SA_L = 16384, SB_H = 32768, SB_L = 32768u + BNG * 4096u;
    const int tid = threadIdx.x;
    const int wid = tid >> 5, lane = tid & 31;
    const int m0 = blockIdx.y * 128, n0 = blockIdx.x * BN;

    const float* pA = A + (size_t)m0 * Kd;
    const float* pB = B + (size_t)n0 * Kd;
    const int rr = tid >> 3;
    const int ch = tid & 7;
    const int NCH = Kd >> 6;

    float acc[2][2 * BNG][4];
#pragma unroll
    for (int i = 0; i < 2; i++)
#pragma unroll
        for (int j = 0; j < 2 * BNG; j++)
#pragma unroll
            for (int q = 0; q < 4; q++) acc[i][j][q] = 0.f;

    float4 rf[(4 + BNG) * 2];
#define LOAD_CHUNK(c)                                                         \
    {                                                                         \
        _Pragma("unroll")                                                     \
        for (int g = 0; g < 4 + BNG; g++) {                                   \
            const float* bp = (g < 4) ? pA : pB;                              \
            int s = (g < 4) ? g : g - 4;                                      \
            const float* src = bp + (size_t)(s * 32 + rr) * Kd + (c) * 64 + ch * 8; \
            rf[g * 2]     = *(const float4*)src;                              \
            rf[g * 2 + 1] = *(const float4*)(src + 4);                        \
        }                                                                     \
    }

    const int mw = (wid & 3) * 32;
    const int nw = (wid >> 2) * (BN / 2);

    LOAD_CHUNK(0);
    for (int c = 0; c < NCH; c++) {
#pragma unroll
        for (int g = 0; g < 4 + BNG; g++) {
            bool isB = g >= 4;
            int s = isB ? g - 4 : g;
            uint4 hi, lo;
            cvt_hilo4(rf[g * 2], rf[g * 2 + 1], hi, lo);
            uint32_t off = SWZ((uint32_t)((s * 32 + rr) * 128 + ch * 16));
            uint32_t hb = isB ? SB_H : SA_H;
            uint32_t lb = isB ? SB_L : SA_L;
            asm volatile("st.shared.v4.b32 [%0], {%1,%2,%3,%4};"
                         :: "r"(sb + hb + off), "r"(hi.x), "r"(hi.y), "r"(hi.z), "r"(hi.w) : "memory");
            asm volatile("st.shared.v4.b32 [%0], {%1,%2,%3,%4};"
                         :: "r"(sb + lb + off), "r"(lo.x), "r"(lo.y), "r"(lo.z), "r"(lo.w) : "memory");
        }
        __syncthreads();
        if (c + 1 < NCH) LOAD_CHUNK(c + 1);

#pragma unroll
        for (int kk = 0; kk < 4; kk++) {
            const uint32_t colb = kk * 32 + (lane >> 4) * 16;
            const int rl = lane & 15;
            uint32_t ah[2][4], al[2][4];
#pragma unroll
            for (int mt = 0; mt < 2; mt++) {
                uint32_t off = SWZ((uint32_t)((mw + mt * 16 + rl) * 128) + colb);
                ldm_x4(sb + SA_H + off, ah[mt][0], ah[mt][1], ah[mt][2], ah[mt][3]);
                ldm_x4(sb + SA_L + off, al[mt][0], al[mt][1], al[mt][2], al[mt][3]);
            }
#pragma unroll
            for (int bt = 0; bt < BNG; bt++) {
                uint32_t off = SWZ((uint32_t)((nw + bt * 16 + rl) * 128) + colb);
                uint32_t bh0, bh1, bh2, bh3, bl0, bl1, bl2, bl3;
                ldm_x4(sb + SB_H + off, bh0, bh1, bh2, bh3);
                ldm_x4(sb + SB_L + off, bl0, bl1, bl2, bl3);
#pragma unroll
                for (int mt = 0; mt < 2; mt++) {
                    float* c0 = acc[mt][bt * 2];
                    float* c1 = acc[mt][bt * 2 + 1];
                    mma_bf16(c0[0], c0[1], c0[2], c0[3],
                             ah[mt][0], ah[mt][1], ah[mt][2], ah[mt][3], bh0, bh2);
                    mma_bf16(c1[0], c1[1], c1[2], c1[3],
                             ah[mt][0], ah[mt][1], ah[mt][2], ah[mt][3], bh1, bh3);
                    mma_bf16(c0[0], c0[1], c0[2], c0[3],
                             al[mt][0], al[mt][1], al[mt][2], al[mt][3], bh0, bh2);
                    mma_bf16(c1[0], c1[1], c1[2], c1[3],
                             al[mt][0], al[mt][1], al[mt][2], al[mt][3], bh1, bh3);
                    mma_bf16(c0[0], c0[1], c0[2], c0[3],
                             ah[mt][0], ah[mt][1], ah[mt][2], ah[mt][3], bl0, bl2);
                    mma_bf16(c1[0], c1[1], c1[2], c1[3],
                             ah[mt][0], ah[mt][1], ah[mt][2], ah[mt][3], bl1, bl3);
                }
            }
        }
        __syncthreads();
    }

    // ---- fused q/k L2-norm + rope (QKV gemm only; warp tile = 32 tokens x 1 head) ----
    if (QKNORM) {
        int cg = n0 + nw;              // warp's global feature base (64-wide)
        int type = cg >> 9;            // 0=q 1=k 2=v
        if (type < 2) {
            int head = (cg >> 6) & 7;
            float sq = sqrtf(__ldg(scl + head));
            float fr[2][2], c16 = (float)((lane & 3) * 2);
#pragma unroll
            for (int j2 = 0; j2 < 2; j2++)
#pragma unroll
                for (int e = 0; e < 2; e++) {
                    float cidx = (float)(j2 * 8) + c16 + (float)e;
                    fr[j2][e] = 3.14159265358979323846f *
                                expf((cidx * 8.0f + (float)head) * (2.302585092994045684f / 128.f));
                }
#pragma unroll
            for (int mt = 0; mt < 2; mt++) {
#pragma unroll
                for (int rh = 0; rh < 2; rh++) {
                    int token = m0 + mw + mt * 16 + (lane >> 2) + rh * 8;
                    float ss = 0.f;
#pragma unroll
                    for (int j = 0; j < 8; j++) {
                        float a0 = acc[mt][j][rh * 2], a1 = acc[mt][j][rh * 2 + 1];
                        ss = fmaf(a0, a0, fmaf(a1, a1, ss));
                    }
                    ss += __shfl_xor_sync(0xffffffffu, ss, 1);
                    ss += __shfl_xor_sync(0xffffffffu, ss, 2);
                    float f = sq * rsqrtf(ss + 1e-6f);
#pragma unroll
                    for (int j = 0; j < 8; j++) {
                        acc[mt][j][rh * 2]     *= f;
                        acc[mt][j][rh * 2 + 1] *= f;
                    }
                    float p = __ldg(pos + token);
#pragma unroll
                    for (int j2 = 0; j2 < 2; j2++)
#pragma unroll
                        for (int e = 0; e < 2; e++) {
                            float th = p * fr[j2][e], cs, sn;
                            __sincosf(th, &sn, &cs);
                            float x1 = acc[mt][j2][rh * 2 + e];
                            float x2 = acc[mt][j2 + 2][rh * 2 + e];
                            acc[mt][j2][rh * 2 + e]     = x1 * cs - x2 * sn;
                            acc[mt][j2 + 2][rh * 2 + e] = x2 * cs + x1 * sn;
                        }
                }
            }
        }
    }

    // ---- store ----
#pragma unroll
    for (int mt = 0; mt < 2; mt++) {
#pragma unroll
        for (int j = 0; j < 2 * BNG; j++) {
            int m = m0 + mw + mt * 16 + (lane >> 2);
            int n = n0 + nw + j * 8 + (lane & 3) * 2;
            float2 v0 = {acc[mt][j][0], acc[mt][j][1]};
            float2 v1 = {acc[mt][j][2], acc[mt][j][3]};
            if (ADD) {
                float2 s0 = *(const float2*)(skip + (size_t)m * N + n);
                float2 s1 = *(const float2*)(skip + (size_t)(m + 8) * N + n);
                v0.x += s0.x; v0.y += s0.y; v1.x += s1.x; v1.y += s1.y;
            }
            *(float2*)(C + (size_t)m * N + n)       = v0;
            *(float2*)(C + (size_t)(m + 8) * N + n) = v1;
        }
    }
}

// ---------------- neighborhood attention ----------------
// grid (i=32, h=8, n=2), 256 thr.  8-lane group per query, fixed-shift softmax.
#define KVSTR 68
__global__ void attn_k(const float* __restrict__ qkv, float* __restrict__ o) {
    extern __shared__ float sm[];
    float* sk = sm;
    float* sv = sm + 7 * 32 * KVSTR;
    const int i = blockIdx.x, h = blockIdx.y, n = blockIdx.z;
    const int si = min(max(i - 3, 0), HH - 7);
    const int tid = threadIdx.x;

    for (int idx = tid; idx < 2 * 7 * 32 * 16; idx += 256) {
        int vsel = idx >= 3584;
        int rem  = vsel ? idx - 3584 : idx;
        int key  = rem >> 4;
        int dg   = rem & 15;
        int t    = n * 1024 + (si + (key >> 5)) * 32 + (key & 31);
        const float* src = qkv + (size_t)t * 1536 + (vsel ? 1024 : 512) + h * 64 + dg * 4;
        float* dst = (vsel ? sv : sk) + key * KVSTR + dg * 4;
        *(float4*)dst = *(const float4*)src;
    }
    __syncthreads();

    const int warp = tid >> 5, lane = tid & 31;
    const int grp = lane >> 3, li = lane & 7;
    const int j = warp * 4 + grp;
    const int t = n * 1024 + i * 32 + j;
    const float* qp = qkv + (size_t)t * 1536 + h * 64 + li * 8;
    const float4 q0 = *(const float4*)qp;
    const float4 q1 = *(const float4*)(qp + 4);
    const int sj = min(max(j - 3, 0), WW - 7);
    const int c0 = min(max(warp * 4 - 3, 0), WW - 7);   // sj of first query in warp

    float l = 0.f;
    float4 o0 = {0, 0, 0, 0}, o1 = {0, 0, 0, 0};
    for (int a = 0; a < 7; a++) {
        const float* ka = sk + a * 32 * KVSTR;
        const float* va = sv + a * 32 * KVSTR;
#pragma unroll
        for (int cc = 0; cc < 10; cc++) {
            int c  = c0 + cc;
            int cl = min(c, 31);
            const float* kp = ka + cl * KVSTR + li * 8;
            float4 k0 = *(const float4*)kp;
            float4 k1 = *(const float4*)(kp + 4);
            float d = q0.x * k0.x + q0.y * k0.y + q0.z * k0.z + q0.w * k0.w
                    + q1.x * k1.x + q1.y * k1.y + q1.z * k1.z + q1.w * k1.w;
            d += __shfl_xor_sync(0xffffffffu, d, 1);
            d += __shfl_xor_sync(0xffffffffu, d, 2);
            d += __shfl_xor_sync(0xffffffffu, d, 4);
            bool in = (c >= sj) && (c < sj + 7);
            float w = in ? __expf(d - 10.0f) : 0.0f;
            const float* vp = va + cl * KVSTR + li * 8;
            float4 v0 = *(const float4*)vp;
            float4 v1 = *(const float4*)(vp + 4);
            l += w;
            o0.x = fmaf(w, v0.x, o0.x); o0.y = fmaf(w, v0.y, o0.y);
            o0.z = fmaf(w, v0.z, o0.z); o0.w = fmaf(w, v0.w, o0.w);
            o1.x = fmaf(w, v1.x, o1.x); o1.y = fmaf(w, v1.y, o1.y);
            o1.z = fmaf(w, v1.z, o1.z); o1.w = fmaf(w, v1.w, o1.w);
        }
    }
    float inv = 1.0f / l;
    o0.x *= inv; o0.y *= inv; o0.z *= inv; o0.w *= inv;
    o1.x *= inv; o1.y *= inv; o1.z *= inv; o1.w *= inv;
    float* op = o + (size_t)t * DMODEL + h * 64 + li * 8;
    *(float4*)op       = o0;
    *(float4*)(op + 4) = o1;
}

// ---------------- launch ----------------
extern "C" void kernel_launch(void* const* d_in, const int* in_sizes, int n_in,
                              void* d_out, int out_size) {
    const float* x      = (const float*)d_in[0];
    const float* pos    = (const float*)d_in[1];
    const float* cond   = (const float*)d_in[2];
    const float* w_cond = (const float*)d_in[3];
    const float* w_qkv  = (const float*)d_in[4];
    const float* scale  = (const float*)d_in[5];
    const float* w_out  = (const float*)d_in[6];
    float* out = (float*)d_out;

    float *p_ns, *p_xn, *p_qkv, *p_o;
    cudaGetSymbolAddress((void**)&p_ns,  g_ns);
    cudaGetSymbolAddress((void**)&p_xn,  g_xn);
    cudaGetSymbolAddress((void**)&p_qkv, g_qkv);
    cudaGetSymbolAddress((void**)&p_o,   g_o);

    const int smem_qkv = 65536;
    const int smem_out = 49152;
    cudaFuncSetAttribute((const void*)gemm_mma<4, false, true>,
                         cudaFuncAttributeMaxDynamicSharedMemorySize, smem_qkv);
    cudaFuncSetAttribute((const void*)gemm_mma<2, true, false>,
                         cudaFuncAttributeMaxDynamicSharedMemorySize, smem_out);

    // 1. norm_scale
    cond_scale_k<<<128, 256>>>(cond, w_cond, p_ns);
    // 2. rms norm (fp32 out)
    rmsnorm_k<<<NTOK, 128>>>(x, p_ns, p_xn);
    // 3. qkv = xn @ w_qkv^T, fused q/k-norm + rope
    gemm_mma<4, false, true><<<dim3(1536 / 128, NTOK / 128), 256, smem_qkv>>>(
        p_xn, w_qkv, nullptr, p_qkv, pos, scale, NTOK, 3 * DMODEL, DMODEL);
    // 4. neighborhood attention
    const int attn_smem = 2 * 7 * 32 * KVSTR * (int)sizeof(float);   // 121856
    cudaFuncSetAttribute(attn_k, cudaFuncAttributeMaxDynamicSharedMemorySize, attn_smem);
    attn_k<<<dim3(HH, NHEADS, 2), 256, attn_smem>>>(p_qkv, p_o);
    // 5. out = o @ w_out^T + skip
    gemm_mma<2, true, false><<<dim3(DMODEL / 64, NTOK / 128), 256, smem_out>>>(
        p_o, w_out, x, out, nullptr, nullptr, NTOK, DMODEL, DMODEL);
}

// round 5
// speedup vs baseline: 1.3185x; 1.3185x over previous
#include <cuda_runtime.h>
#include <cuda_bf16.h>
#include <cuda_fp16.h>
#include <math.h>
#include <stdint.h>

#define NTOK   2048
#define DMODEL 512
#define NHEADS 8
#define DHEAD  64
#define CONDD  768
#define HH     32
#define WW     32

// ---------------- scratch ----------------
__device__ float g_ns [2 * DMODEL];
__device__ float g_xn [NTOK * DMODEL];
__device__ float g_qkv[NTOK * 3 * DMODEL];
__device__ float g_o  [NTOK * DMODEL];

__device__ __forceinline__ float warp_sum(float v) {
    v += __shfl_xor_sync(0xffffffffu, v, 16);
    v += __shfl_xor_sync(0xffffffffu, v, 8);
    v += __shfl_xor_sync(0xffffffffu, v, 4);
    v += __shfl_xor_sync(0xffffffffu, v, 2);
    v += __shfl_xor_sync(0xffffffffu, v, 1);
    return v;
}
__device__ __forceinline__ uint32_t smem_u32(const void* p) {
    return (uint32_t)__cvta_generic_to_shared((void*)p);
}
#define SWZ(o) ((o) ^ ((((uint32_t)(o)) >> 3) & 0x70))

__device__ __forceinline__ void ldm_x4(uint32_t addr, uint32_t& r0, uint32_t& r1,
                                       uint32_t& r2, uint32_t& r3) {
    asm volatile("ldmatrix.sync.aligned.m8n8.x4.shared.b16 {%0,%1,%2,%3}, [%4];"
                 : "=r"(r0), "=r"(r1), "=r"(r2), "=r"(r3) : "r"(addr));
}
__device__ __forceinline__ void mma_bf16(float& c0, float& c1, float& c2, float& c3,
                                         uint32_t a0, uint32_t a1, uint32_t a2, uint32_t a3,
                                         uint32_t b0, uint32_t b1) {
    asm volatile(
        "mma.sync.aligned.m16n8k16.row.col.f32.bf16.bf16.f32 "
        "{%0,%1,%2,%3}, {%4,%5,%6,%7}, {%8,%9}, {%0,%1,%2,%3};"
        : "+f"(c0), "+f"(c1), "+f"(c2), "+f"(c3)
        : "r"(a0), "r"(a1), "r"(a2), "r"(a3), "r"(b0), "r"(b1));
}

// fp32x8 -> bf16 hi/lo uint4 pair
__device__ __forceinline__ void cvt_hilo4(float4 f0, float4 f1, uint4& hi, uint4& lo) {
    __nv_bfloat162 h0 = __floats2bfloat162_rn(f0.x, f0.y);
    __nv_bfloat162 h1 = __floats2bfloat162_rn(f0.z, f0.w);
    __nv_bfloat162 h2 = __floats2bfloat162_rn(f1.x, f1.y);
    __nv_bfloat162 h3 = __floats2bfloat162_rn(f1.z, f1.w);
    float2 g0 = __bfloat1622float2(h0), g1 = __bfloat1622float2(h1);
    float2 g2 = __bfloat1622float2(h2), g3 = __bfloat1622float2(h3);
    __nv_bfloat162 l0 = __floats2bfloat162_rn(f0.x - g0.x, f0.y - g0.y);
    __nv_bfloat162 l1 = __floats2bfloat162_rn(f0.z - g1.x, f0.w - g1.y);
    __nv_bfloat162 l2 = __floats2bfloat162_rn(f1.x - g2.x, f1.y - g2.y);
    __nv_bfloat162 l3 = __floats2bfloat162_rn(f1.z - g3.x, f1.w - g3.y);
    hi.x = *(uint32_t*)&h0; hi.y = *(uint32_t*)&h1; hi.z = *(uint32_t*)&h2; hi.w = *(uint32_t*)&h3;
    lo.x = *(uint32_t*)&l0; lo.y = *(uint32_t*)&l1; lo.z = *(uint32_t*)&l2; lo.w = *(uint32_t*)&l3;
}

// ---------------- 1. norm_scale = cond @ w_cond^T + 1 ----------------
__global__ void cond_scale_k(const float* __restrict__ cond,
                             const float* __restrict__ w_cond,
                             float* __restrict__ ns) {
    int gw   = (blockIdx.x * blockDim.x + threadIdx.x) >> 5;
    int lane = threadIdx.x & 31;
    int n = gw >> 9, d = gw & 511;
    const float* wr = w_cond + (size_t)d * CONDD;
    const float* cr = cond   + (size_t)n * CONDD;
    float s = 0.f;
    for (int k = lane; k < CONDD; k += 32) s = fmaf(wr[k], cr[k], s);
    s = warp_sum(s);
    if (lane == 0) ns[n * DMODEL + d] = s + 1.0f;
}

// ---------------- 2. RMS norm * norm_scale (fp32 out) ----------------
__global__ void rmsnorm_k(const float* __restrict__ x,
                          const float* __restrict__ ns,
                          float* __restrict__ xn) {
    int t = blockIdx.x;
    int n = t >> 10;
    float4 v = ((const float4*)(x + (size_t)t * DMODEL))[threadIdx.x];
    float ss = v.x*v.x + v.y*v.y + v.z*v.z + v.w*v.w;
    ss = warp_sum(ss);
    __shared__ float sred[4];
    int w = threadIdx.x >> 5, l = threadIdx.x & 31;
    if (l == 0) sred[w] = ss;
    __syncthreads();
    float tot = sred[0] + sred[1] + sred[2] + sred[3];
    float inv = rsqrtf(tot * (1.0f / DMODEL) + 1e-6f);
    float4 s4 = ((const float4*)(ns + (size_t)n * DMODEL))[threadIdx.x];
    float4 o;
    o.x = v.x * s4.x * inv; o.y = v.y * s4.y * inv;
    o.z = v.z * s4.z * inv; o.w = v.w * s4.w * inv;
    ((float4*)(xn + (size_t)t * DMODEL))[threadIdx.x] = o;
}

// ---------------- mma.sync GEMM, fused fp32->hi/lo, optional fused qk-norm+rope ----------------
template<int BNG, bool ADD, bool QKNORM>
__global__ void __launch_bounds__(256, 1)
gemm_mma(const float* __restrict__ A, const float* __restrict__ B,
         const float* __restrict__ skip, float* __restrict__ C,
         const float* __restrict__ pos, const float* __restrict__ scl,
         int M, int N, int Kd) {
    constexpr int BN = BNG * 32;
    extern __shared__ char smraw[];
    const uint32_t sb = smem_u32(smraw);
    const uint32_t SA_H = 0, SA_L = 16384, SB_H = 32768, SB_L = 32768u + BNG * 4096u;
    const int tid = threadIdx.x;
    const int wid = tid >> 5, lane = tid & 31;
    const int m0 = blockIdx.y * 128, n0 = blockIdx.x * BN;

    const float* pA = A + (size_t)m0 * Kd;
    const float* pB = B + (size_t)n0 * Kd;
    const int rr = tid >> 3;
    const int ch = tid & 7;
    const int NCH = Kd >> 6;

    float acc[2][2 * BNG][4];
#pragma unroll
    for (int i = 0; i < 2; i++)
#pragma unroll
        for (int j = 0; j < 2 * BNG; j++)
#pragma unroll
            for (int q = 0; q < 4; q++) acc[i][j][q] = 0.f;

    float4 rf[(4 + BNG) * 2];
#define LOAD_CHUNK(c)                                                         \
    {                                                                         \
        _Pragma("unroll")                                                     \
        for (int g = 0; g < 4 + BNG; g++) {                                   \
            const float* bp = (g < 4) ? pA : pB;                              \
            int s = (g < 4) ? g : g - 4;                                      \
            const float* src = bp + (size_t)(s * 32 + rr) * Kd + (c) * 64 + ch * 8; \
            rf[g * 2]     = *(const float4*)src;                              \
            rf[g * 2 + 1] = *(const float4*)(src + 4);                        \
        }                                                                     \
    }

    const int mw = (wid & 3) * 32;
    const int nw = (wid >> 2) * (BN / 2);

    LOAD_CHUNK(0);
    for (int c = 0; c < NCH; c++) {
#pragma unroll
        for (int g = 0; g < 4 + BNG; g++) {
            bool isB = g >= 4;
            int s = isB ? g - 4 : g;
            uint4 hi, lo;
            cvt_hilo4(rf[g * 2], rf[g * 2 + 1], hi, lo);
            uint32_t off = SWZ((uint32_t)((s * 32 + rr) * 128 + ch * 16));
            uint32_t hb = isB ? SB_H : SA_H;
            uint32_t lb = isB ? SB_L : SA_L;
            asm volatile("st.shared.v4.b32 [%0], {%1,%2,%3,%4};"
                         :: "r"(sb + hb + off), "r"(hi.x), "r"(hi.y), "r"(hi.z), "r"(hi.w) : "memory");
            asm volatile("st.shared.v4.b32 [%0], {%1,%2,%3,%4};"
                         :: "r"(sb + lb + off), "r"(lo.x), "r"(lo.y), "r"(lo.z), "r"(lo.w) : "memory");
        }
        __syncthreads();
        if (c + 1 < NCH) LOAD_CHUNK(c + 1);

#pragma unroll
        for (int kk = 0; kk < 4; kk++) {
            const uint32_t colb = kk * 32 + (lane >> 4) * 16;
            const int rl = lane & 15;
            uint32_t ah[2][4], al[2][4];
#pragma unroll
            for (int mt = 0; mt < 2; mt++) {
                uint32_t off = SWZ((uint32_t)((mw + mt * 16 + rl) * 128) + colb);
                ldm_x4(sb + SA_H + off, ah[mt][0], ah[mt][1], ah[mt][2], ah[mt][3]);
                ldm_x4(sb + SA_L + off, al[mt][0], al[mt][1], al[mt][2], al[mt][3]);
            }
#pragma unroll
            for (int bt = 0; bt < BNG; bt++) {
                uint32_t off = SWZ((uint32_t)((nw + bt * 16 + rl) * 128) + colb);
                uint32_t bh0, bh1, bh2, bh3, bl0, bl1, bl2, bl3;
                ldm_x4(sb + SB_H + off, bh0, bh1, bh2, bh3);
                ldm_x4(sb + SB_L + off, bl0, bl1, bl2, bl3);
#pragma unroll
                for (int mt = 0; mt < 2; mt++) {
                    float* c0 = acc[mt][bt * 2];
                    float* c1 = acc[mt][bt * 2 + 1];
                    mma_bf16(c0[0], c0[1], c0[2], c0[3],
                             ah[mt][0], ah[mt][1], ah[mt][2], ah[mt][3], bh0, bh2);
                    mma_bf16(c1[0], c1[1], c1[2], c1[3],
                             ah[mt][0], ah[mt][1], ah[mt][2], ah[mt][3], bh1, bh3);
                    mma_bf16(c0[0], c0[1], c0[2], c0[3],
                             al[mt][0], al[mt][1], al[mt][2], al[mt][3], bh0, bh2);
                    mma_bf16(c1[0], c1[1], c1[2], c1[3],
                             al[mt][0], al[mt][1], al[mt][2], al[mt][3], bh1, bh3);
                    mma_bf16(c0[0], c0[1], c0[2], c0[3],
                             ah[mt][0], ah[mt][1], ah[mt][2], ah[mt][3], bl0, bl2);
                    mma_bf16(c1[0], c1[1], c1[2], c1[3],
                             ah[mt][0], ah[mt][1], ah[mt][2], ah[mt][3], bl1, bl3);
                }
            }
        }
        __syncthreads();
    }

    // ---- fused q/k L2-norm + rope ----
    if (QKNORM) {
        int cg = n0 + nw;
        int type = cg >> 9;
        if (type < 2) {
            int head = (cg >> 6) & 7;
            float sq = sqrtf(__ldg(scl + head));
            float fr[2][2], c16 = (float)((lane & 3) * 2);
#pragma unroll
            for (int j2 = 0; j2 < 2; j2++)
#pragma unroll
                for (int e = 0; e < 2; e++) {
                    float cidx = (float)(j2 * 8) + c16 + (float)e;
                    fr[j2][e] = 3.14159265358979323846f *
                                expf((cidx * 8.0f + (float)head) * (2.302585092994045684f / 128.f));
                }
#pragma unroll
            for (int mt = 0; mt < 2; mt++) {
#pragma unroll
                for (int rh = 0; rh < 2; rh++) {
                    int token = m0 + mw + mt * 16 + (lane >> 2) + rh * 8;
                    float ss = 0.f;
#pragma unroll
                    for (int j = 0; j < 8; j++) {
                        float a0 = acc[mt][j][rh * 2], a1 = acc[mt][j][rh * 2 + 1];
                        ss = fmaf(a0, a0, fmaf(a1, a1, ss));
                    }
                    ss += __shfl_xor_sync(0xffffffffu, ss, 1);
                    ss += __shfl_xor_sync(0xffffffffu, ss, 2);
                    float f = sq * rsqrtf(ss + 1e-6f);
#pragma unroll
                    for (int j = 0; j < 8; j++) {
                        acc[mt][j][rh * 2]     *= f;
                        acc[mt][j][rh * 2 + 1] *= f;
                    }
                    float p = __ldg(pos + token);
#pragma unroll
                    for (int j2 = 0; j2 < 2; j2++)
#pragma unroll
                        for (int e = 0; e < 2; e++) {
                            float th = p * fr[j2][e], cs, sn;
                            __sincosf(th, &sn, &cs);
                            float x1 = acc[mt][j2][rh * 2 + e];
                            float x2 = acc[mt][j2 + 2][rh * 2 + e];
                            acc[mt][j2][rh * 2 + e]     = x1 * cs - x2 * sn;
                            acc[mt][j2 + 2][rh * 2 + e] = x2 * cs + x1 * sn;
                        }
                }
            }
        }
    }

    // ---- store ----
#pragma unroll
    for (int mt = 0; mt < 2; mt++) {
#pragma unroll
        for (int j = 0; j < 2 * BNG; j++) {
            int m = m0 + mw + mt * 16 + (lane >> 2);
            int n = n0 + nw + j * 8 + (lane & 3) * 2;
            float2 v0 = {acc[mt][j][0], acc[mt][j][1]};
            float2 v1 = {acc[mt][j][2], acc[mt][j][3]};
            if (ADD) {
                float2 s0 = *(const float2*)(skip + (size_t)m * N + n);
                float2 s1 = *(const float2*)(skip + (size_t)(m + 8) * N + n);
                v0.x += s0.x; v0.y += s0.y; v1.x += s1.x; v1.y += s1.y;
            }
            *(float2*)(C + (size_t)m * N + n)       = v0;
            *(float2*)(C + (size_t)(m + 8) * N + n) = v1;
        }
    }
}

// ---------------- neighborhood attention (fp16 K/V staging, fp32 math) ----------------
// grid (i=32, h=8, n=2), 256 thr, 3 CTAs/SM.
__global__ void __launch_bounds__(256, 3) attn_k(const float* __restrict__ qkv,
                                                 float* __restrict__ o) {
    extern __shared__ __half smh[];
    __half* sk = smh;                     // [224][64] halves
    __half* sv = smh + 7 * 32 * 64;
    const int i = blockIdx.x, h = blockIdx.y, n = blockIdx.z;
    const int si = min(max(i - 3, 0), HH - 7);
    const int tid = threadIdx.x;

    // stage K,V as fp16: 2 arrays x 224 keys x 8 chunks of 8 dims
    for (int idx = tid; idx < 2 * 224 * 8; idx += 256) {
        int vsel = idx >= 1792;
        int rem  = vsel ? idx - 1792 : idx;
        int key  = rem >> 3;
        int dg   = rem & 7;
        int t    = n * 1024 + (si + (key >> 5)) * 32 + (key & 31);
        const float* src = qkv + (size_t)t * 1536 + (vsel ? 1024 : 512) + h * 64 + dg * 8;
        float4 f0 = *(const float4*)src;
        float4 f1 = *(const float4*)(src + 4);
        __half2 u0 = __float22half2_rn({f0.x, f0.y});
        __half2 u1 = __float22half2_rn({f0.z, f0.w});
        __half2 u2 = __float22half2_rn({f1.x, f1.y});
        __half2 u3 = __float22half2_rn({f1.z, f1.w});
        uint4 u = { *(uint32_t*)&u0, *(uint32_t*)&u1, *(uint32_t*)&u2, *(uint32_t*)&u3 };
        *(uint4*)((vsel ? sv : sk) + key * 64 + dg * 8) = u;
    }
    __syncthreads();

    const int warp = tid >> 5, lane = tid & 31;
    const int grp = lane >> 3, li = lane & 7;
    const int j = warp * 4 + grp;
    const int t = n * 1024 + i * 32 + j;
    const float* qp = qkv + (size_t)t * 1536 + h * 64 + li * 8;
    const float4 q0 = *(const float4*)qp;
    const float4 q1 = *(const float4*)(qp + 4);
    const int sj = min(max(j - 3, 0), WW - 7);
    const int c0 = min(max(warp * 4 - 3, 0), WW - 7);

    float l = 0.f;
    float4 o0 = {0, 0, 0, 0}, o1 = {0, 0, 0, 0};
    for (int a = 0; a < 7; a++) {
        const __half* ka = sk + a * 32 * 64;
        const __half* va = sv + a * 32 * 64;
#pragma unroll
        for (int cc = 0; cc < 10; cc++) {
            int c  = c0 + cc;
            int cl = min(c, 31);
            uint4 ku = *(const uint4*)(ka + cl * 64 + li * 8);
            float2 k0 = __half22float2(*(__half2*)&ku.x);
            float2 k1 = __half22float2(*(__half2*)&ku.y);
            float2 k2 = __half22float2(*(__half2*)&ku.z);
            float2 k3 = __half22float2(*(__half2*)&ku.w);
            float d = q0.x * k0.x + q0.y * k0.y + q0.z * k1.x + q0.w * k1.y
                    + q1.x * k2.x + q1.y * k2.y + q1.z * k3.x + q1.w * k3.y;
            d += __shfl_xor_sync(0xffffffffu, d, 1);
            d += __shfl_xor_sync(0xffffffffu, d, 2);
            d += __shfl_xor_sync(0xffffffffu, d, 4);
            bool in = (c >= sj) && (c < sj + 7);
            float w = in ? __expf(d - 10.0f) : 0.0f;
            uint4 vu = *(const uint4*)(va + cl * 64 + li * 8);
            float2 v0 = __half22float2(*(__half2*)&vu.x);
            float2 v1 = __half22float2(*(__half2*)&vu.y);
            float2 v2 = __half22float2(*(__half2*)&vu.z);
            float2 v3 = __half22float2(*(__half2*)&vu.w);
            l += w;
            o0.x = fmaf(w, v0.x, o0.x); o0.y = fmaf(w, v0.y, o0.y);
            o0.z = fmaf(w, v1.x, o0.z); o0.w = fmaf(w, v1.y, o0.w);
            o1.x = fmaf(w, v2.x, o1.x); o1.y = fmaf(w, v2.y, o1.y);
            o1.z = fmaf(w, v3.x, o1.z); o1.w = fmaf(w, v3.y, o1.w);
        }
    }
    float inv = 1.0f / l;
    o0.x *= inv; o0.y *= inv; o0.z *= inv; o0.w *= inv;
    o1.x *= inv; o1.y *= inv; o1.z *= inv; o1.w *= inv;
    float* op = o + (size_t)t * DMODEL + h * 64 + li * 8;
    *(float4*)op       = o0;
    *(float4*)(op + 4) = o1;
}

// ---------------- launch ----------------
extern "C" void kernel_launch(void* const* d_in, const int* in_sizes, int n_in,
                              void* d_out, int out_size) {
    const float* x      = (const float*)d_in[0];
    const float* pos    = (const float*)d_in[1];
    const float* cond   = (const float*)d_in[2];
    const float* w_cond = (const float*)d_in[3];
    const float* w_qkv  = (const float*)d_in[4];
    const float* scale  = (const float*)d_in[5];
    const float* w_out  = (const float*)d_in[6];
    float* out = (float*)d_out;

    float *p_ns, *p_xn, *p_qkv, *p_o;
    cudaGetSymbolAddress((void**)&p_ns,  g_ns);
    cudaGetSymbolAddress((void**)&p_xn,  g_xn);
    cudaGetSymbolAddress((void**)&p_qkv, g_qkv);
    cudaGetSymbolAddress((void**)&p_o,   g_o);

    const int smem_qkv = 65536;
    const int smem_out = 49152;
    cudaFuncSetAttribute((const void*)gemm_mma<4, false, true>,
                         cudaFuncAttributeMaxDynamicSharedMemorySize, smem_qkv);
    cudaFuncSetAttribute((const void*)gemm_mma<2, true, false>,
                         cudaFuncAttributeMaxDynamicSharedMemorySize, smem_out);

    // 1. norm_scale
    cond_scale_k<<<128, 256>>>(cond, w_cond, p_ns);
    // 2. rms norm (fp32 out)
    rmsnorm_k<<<NTOK, 128>>>(x, p_ns, p_xn);
    // 3. qkv = xn @ w_qkv^T, fused q/k-norm + rope
    gemm_mma<4, false, true><<<dim3(1536 / 128, NTOK / 128), 256, smem_qkv>>>(
        p_xn, w_qkv, nullptr, p_qkv, pos, scale, NTOK, 3 * DMODEL, DMODEL);
    // 4. neighborhood attention (fp16 staged K/V)
    const int attn_smem = 2 * 7 * 32 * 64 * (int)sizeof(__half);   // 57344
    cudaFuncSetAttribute(attn_k, cudaFuncAttributeMaxDynamicSharedMemorySize, attn_smem);
    attn_k<<<dim3(HH, NHEADS, 2), 256, attn_smem>>>(p_qkv, p_o);
    // 5. out = o @ w_out^T + skip
    gemm_mma<2, true, false><<<dim3(DMODEL / 64, NTOK / 128), 256, smem_out>>>(
        p_o, w_out, x, out, nullptr, nullptr, NTOK, DMODEL, DMODEL);
}